// round 1
// baseline (speedup 1.0000x reference)
#include <cuda_runtime.h>
#include <cuda_bf16.h>
#include <math.h>

// Problem dims
#define BB 512
#define TN 300
#define DD 200
#define HH 128
#define GG 512   // 4*H

// ---------------- static device scratch (no allocations allowed) ----------------
__device__ float g_xpA[(size_t)TN * BB * GG];      // 314.6 MB
__device__ float g_xpB[(size_t)TN * BB * GG];      // 314.6 MB
__device__ float g_y0 [(size_t)TN * BB * 2 * HH];  // 157 MB  [t][b][256]
__device__ float g_f1 [(size_t)TN * BB * HH];      // 78.6 MB [t][b][128]
__device__ float g_r1 [(size_t)TN * BB * HH];      // 78.6 MB
__device__ float g_whhT[4 * HH * GG];              // 4 x [128][512]
__device__ float g_wl1T[456 * HH];                 // [456][128]
__device__ float g_pooled[BB * HH];

__device__ __forceinline__ float sigmoidf_(float x) { return 1.f / (1.f + expf(-x)); }

__device__ __forceinline__ void atomicMaxF(float* addr, float v) {
    if (v >= 0.f) atomicMax((int*)addr, __float_as_int(v));
    else          atomicMin((unsigned int*)addr, __float_as_uint(v));
}

// ---------------- small helpers ----------------
__global__ void transpose_kernel(const float* __restrict__ in, float* __restrict__ out,
                                 int rows, int cols) {
    int idx = blockIdx.x * blockDim.x + threadIdx.x;
    if (idx < rows * cols) {
        int r = idx / cols, c = idx % cols;
        out[c * rows + r] = in[idx];
    }
}

__global__ void init_pooled_kernel(float* __restrict__ p) {
    int idx = blockIdx.x * blockDim.x + threadIdx.x;
    if (idx < BB * HH) p[idx] = -2.0f;
}

// ---------------- projection GEMM: C[m][512] = A[t,b,:] @ W^T + b1 + b2 ----------------
// m = t*512 + b ; A row offset = t*strideT + b*strideB ; W is [512][K] row-major
#define GBM 128
#define GBN 128
#define GBK 8
__global__ __launch_bounds__(256) void proj_gemm(
    const float* __restrict__ A, int strideT, int strideB_,
    const float* __restrict__ W, int K,
    const float* __restrict__ bias1, const float* __restrict__ bias2,
    float* __restrict__ C) {
    __shared__ float As[GBK][GBM];
    __shared__ float Bs[GBK][GBN];
    int tid = threadIdx.x;
    int m0 = blockIdx.x * GBM;
    int n0 = blockIdx.y * GBN;

    int ar = tid >> 1, ak = (tid & 1) * 4;
    int row = m0 + ar;
    int tt = row >> 9, bb = row & 511;
    const float* Aptr = A + (size_t)tt * strideT + (size_t)bb * strideB_;
    int bn = tid >> 1, bk = (tid & 1) * 4;
    const float* Wptr = W + (size_t)(n0 + bn) * K;

    int ty = tid >> 4, tx = tid & 15;
    float acc[8][8] = {};
    int nkt = K >> 3;
    for (int kt = 0; kt < nkt; kt++) {
        float4 av = *(const float4*)(Aptr + kt * 8 + ak);
        float4 bv = *(const float4*)(Wptr + kt * 8 + bk);
        As[ak + 0][ar] = av.x; As[ak + 1][ar] = av.y;
        As[ak + 2][ar] = av.z; As[ak + 3][ar] = av.w;
        Bs[bk + 0][bn] = bv.x; Bs[bk + 1][bn] = bv.y;
        Bs[bk + 2][bn] = bv.z; Bs[bk + 3][bn] = bv.w;
        __syncthreads();
#pragma unroll
        for (int k = 0; k < GBK; k++) {
            float regA[8], regB[8];
            *(float4*)&regA[0] = *(const float4*)&As[k][ty * 8];
            *(float4*)&regA[4] = *(const float4*)&As[k][ty * 8 + 4];
            *(float4*)&regB[0] = *(const float4*)&Bs[k][tx * 8];
            *(float4*)&regB[4] = *(const float4*)&Bs[k][tx * 8 + 4];
#pragma unroll
            for (int i = 0; i < 8; i++)
#pragma unroll
                for (int j = 0; j < 8; j++)
                    acc[i][j] += regA[i] * regB[j];
        }
        __syncthreads();
    }
#pragma unroll
    for (int i = 0; i < 8; i++) {
        int m = m0 + ty * 8 + i;
        float* crow = C + (size_t)m * 512 + n0;
#pragma unroll
        for (int j = 0; j < 8; j++) {
            int n = tx * 8 + j;
            crow[n] = acc[i][j] + bias1[n0 + n] + bias2[n0 + n];
        }
    }
}

// ---------------- fused bidirectional LSTM recurrence ----------------
// grid: 128 blocks = 2 dirs x 64 row-slices (8 batch rows each). 256 threads.
// thread: hcol = tid&127, owns 4 rows (tid>>7 selects half), 4 gates each.
__global__ __launch_bounds__(256) void lstm_kernel(
    const float* __restrict__ xpF, const float* __restrict__ xpB,
    const float* __restrict__ whhTF, const float* __restrict__ whhTB,
    const float* __restrict__ hf,
    float* __restrict__ outF, float* __restrict__ outB, int outStride) {
    __shared__ float hsh[2][8][HH];
    int dir = blockIdx.x & 1;
    int rb = (blockIdx.x >> 1) * 8;
    const float* xp   = dir ? xpB   : xpF;
    const float* whhT = dir ? whhTB : whhTF;
    float*       out  = dir ? outB  : outF;
    int tid = threadIdx.x;
    int hcol = tid & 127;
    int r0 = (tid >> 7) * 4;
    float hfv = hf[hcol];
    float c[4];
#pragma unroll
    for (int r = 0; r < 4; r++) { c[r] = hfv; hsh[0][r0 + r][hcol] = hfv; }
    __syncthreads();

    for (int t = 0; t < TN; t++) {
        int tef = dir ? (TN - 1 - t) : t;
        int cur = t & 1;
        float acc[4][4];
        size_t rowbase = ((size_t)tef * BB + rb + r0) * GG + hcol;
#pragma unroll
        for (int r = 0; r < 4; r++) {
            const float* xr = xp + rowbase + (size_t)r * GG;
            acc[r][0] = xr[0];   acc[r][1] = xr[128];
            acc[r][2] = xr[256]; acc[r][3] = xr[384];
        }
        const float* wp = whhT + hcol;
#pragma unroll 4
        for (int k = 0; k < HH; k++) {
            float w0 = wp[0], w1 = wp[128], w2 = wp[256], w3 = wp[384];
            wp += GG;
#pragma unroll
            for (int r = 0; r < 4; r++) {
                float hv = hsh[cur][r0 + r][k];
                acc[r][0] += hv * w0; acc[r][1] += hv * w1;
                acc[r][2] += hv * w2; acc[r][3] += hv * w3;
            }
        }
#pragma unroll
        for (int r = 0; r < 4; r++) {
            float ig = sigmoidf_(acc[r][0]);
            float fg = sigmoidf_(acc[r][1]);
            float cc = tanhf(acc[r][2]);
            float og = sigmoidf_(acc[r][3]);
            float cv = fg * c[r] + ig * cc;
            c[r] = cv;
            float hv = og * tanhf(cv);
            hsh[cur ^ 1][r0 + r][hcol] = hv;
            out[((size_t)tef * BB + rb + r0 + r) * outStride + hcol] = hv;
        }
        __syncthreads();
    }
}

// ---------------- classifier: h = tanh(data @ w_l1^T), max over t ----------------
#define CTT 16
__global__ __launch_bounds__(256) void cls_kernel(
    const float* __restrict__ f1, const float* __restrict__ r1,
    const float* __restrict__ bx, const float* __restrict__ hf,
    const float* __restrict__ wl1T, float* __restrict__ pooled) {
    __shared__ float ds[CTT][456];
    int b = blockIdx.x;
    int tile = blockIdx.y;
    int tid = threadIdx.x;
    for (int idx = tid; idx < CTT * 456; idx += 256) {
        int tt = idx / 456, f = idx % 456;
        int t = tile * CTT + tt;
        float v = 0.f;
        if (t < TN) {
            if (f < 128) {
                v = (t == 0) ? hf[f] : f1[((size_t)t * BB + b) * HH + f];
            } else if (f < 328) {
                v = bx[(size_t)b * TN * DD + (size_t)t * DD + (f - 128)];
            } else {
                int j = f - 328;
                v = (t == TN - 1) ? hf[j] : r1[((size_t)(TN - 2 - t) * BB + b) * HH + j];
            }
        }
        ds[tt][f] = v;
    }
    __syncthreads();

    int o2 = (tid & 63) * 2;
    int tsub = tid >> 6;  // 0..3
    float acc[4][2];
#pragma unroll
    for (int q = 0; q < 4; q++) { acc[q][0] = 0.f; acc[q][1] = 0.f; }
    for (int f = 0; f < 456; f++) {
        float2 w = *(const float2*)(wl1T + f * HH + o2);
#pragma unroll
        for (int q = 0; q < 4; q++) {
            float dv = ds[tsub + q * 4][f];
            acc[q][0] += dv * w.x;
            acc[q][1] += dv * w.y;
        }
    }
    float m0v = -2.f, m1v = -2.f;
#pragma unroll
    for (int q = 0; q < 4; q++) {
        int t = tile * CTT + tsub + q * 4;
        if (t < TN) {
            m0v = fmaxf(m0v, tanhf(acc[q][0]));
            m1v = fmaxf(m1v, tanhf(acc[q][1]));
        }
    }
    atomicMaxF(&pooled[b * HH + o2],     m0v);
    atomicMaxF(&pooled[b * HH + o2 + 1], m1v);
}

// ---------------- final: out = pooled @ w_l2^T + b_l2 ; append b_y ----------------
__global__ void out_kernel(const float* __restrict__ pooled,
                           const float* __restrict__ wl2, const float* __restrict__ bl2,
                           const int* __restrict__ by, float* __restrict__ outb,
                           int out_size) {
    __shared__ float sh[128];
    int b = blockIdx.x, tid = threadIdx.x;
    float p = pooled[b * 128 + tid];
    for (int o = 0; o < 4; o++) {
        float v = p * wl2[o * 128 + tid];
        sh[tid] = v;
        __syncthreads();
        if (tid < 64) sh[tid] += sh[tid + 64];
        __syncthreads();
        if (tid < 32) {
            float s = sh[tid] + sh[tid + 32];
            for (int off = 16; off; off >>= 1) s += __shfl_down_sync(0xffffffffu, s, off);
            if (tid == 0) outb[b * 4 + o] = s + bl2[o];
        }
        __syncthreads();
    }
    if (tid == 0 && out_size >= BB * 4 + BB) outb[BB * 4 + b] = (float)by[b];
}

// ---------------- launch ----------------
extern "C" void kernel_launch(void* const* d_in, const int* in_sizes, int n_in,
                              void* d_out, int out_size) {
    const float* bx       = (const float*)d_in[0];
    const int*   by       = (const int*)  d_in[1];
    const float* hf       = (const float*)d_in[2];
    const float* w_ih[4]  = { (const float*)d_in[3],  (const float*)d_in[7],
                              (const float*)d_in[11], (const float*)d_in[15] };
    const float* w_hh[4]  = { (const float*)d_in[4],  (const float*)d_in[8],
                              (const float*)d_in[12], (const float*)d_in[16] };
    const float* b_ih[4]  = { (const float*)d_in[5],  (const float*)d_in[9],
                              (const float*)d_in[13], (const float*)d_in[17] };
    const float* b_hh[4]  = { (const float*)d_in[6],  (const float*)d_in[10],
                              (const float*)d_in[14], (const float*)d_in[18] };
    const float* wl1      = (const float*)d_in[19];
    const float* wl2      = (const float*)d_in[20];
    const float* bl2      = (const float*)d_in[21];
    float* outb = (float*)d_out;

    float *xpA, *xpB, *y0, *f1, *r1, *whhT, *wl1T, *pooled;
    cudaGetSymbolAddress((void**)&xpA,    g_xpA);
    cudaGetSymbolAddress((void**)&xpB,    g_xpB);
    cudaGetSymbolAddress((void**)&y0,     g_y0);
    cudaGetSymbolAddress((void**)&f1,     g_f1);
    cudaGetSymbolAddress((void**)&r1,     g_r1);
    cudaGetSymbolAddress((void**)&whhT,   g_whhT);
    cudaGetSymbolAddress((void**)&wl1T,   g_wl1T);
    cudaGetSymbolAddress((void**)&pooled, g_pooled);

    // Pre-transposes + pooled init
    for (int i = 0; i < 4; i++)
        transpose_kernel<<<(GG * HH + 255) / 256, 256>>>(w_hh[i], whhT + i * GG * HH, GG, HH);
    transpose_kernel<<<(HH * 456 + 255) / 256, 256>>>(wl1, wl1T, HH, 456);
    init_pooled_kernel<<<(BB * HH + 255) / 256, 256>>>(pooled);

    dim3 pg(TN * BB / GBM, GG / GBN);  // (1200, 4)

    // Layer 0 projections: A = b_x [b][t][d]
    proj_gemm<<<pg, 256>>>(bx, DD, TN * DD, w_ih[0], DD, b_ih[0], b_hh[0], xpA);
    proj_gemm<<<pg, 256>>>(bx, DD, TN * DD, w_ih[1], DD, b_ih[1], b_hh[1], xpB);

    // Layer 0 recurrence (both directions) -> y0 [t][b][256]
    lstm_kernel<<<128, 256>>>(xpA, xpB, whhT, whhT + GG * HH, hf, y0, y0 + HH, 2 * HH);

    // Layer 1 projections: A = y0 [t][b][256]
    proj_gemm<<<pg, 256>>>(y0, BB * 2 * HH, 2 * HH, w_ih[2], 2 * HH, b_ih[2], b_hh[2], xpA);
    proj_gemm<<<pg, 256>>>(y0, BB * 2 * HH, 2 * HH, w_ih[3], 2 * HH, b_ih[3], b_hh[3], xpB);

    // Layer 1 recurrence -> f1, r1
    lstm_kernel<<<128, 256>>>(xpA, xpB, whhT + 2 * GG * HH, whhT + 3 * GG * HH, hf, f1, r1, HH);

    // Classifier + maxpool
    dim3 cg(BB, (TN + CTT - 1) / CTT);
    cls_kernel<<<cg, 256>>>(f1, r1, bx, hf, wl1T, pooled);

    // Head + b_y passthrough
    out_kernel<<<BB, 128>>>(pooled, wl2, bl2, by, outb, out_size);
}

// round 3
// speedup vs baseline: 1.1704x; 1.1704x over previous
#include <cuda_runtime.h>
#include <cuda_bf16.h>
#include <math.h>
#include <cstdint>

// Problem dims
#define BB 512
#define TN 300
#define DD 200
#define HH 128
#define GG 512   // 4*H
#define MM (TN*BB)      // 153600 rows
#define KP 256          // padded K per segment

// ---------------- static device scratch ----------------
__device__ float g_xpA[(size_t)TN * BB * GG];
__device__ float g_xpB[(size_t)TN * BB * GG];
__device__ float g_y0 [(size_t)TN * BB * 2 * HH];
__device__ float g_f1 [(size_t)TN * BB * HH];
__device__ float g_r1 [(size_t)TN * BB * HH];
__device__ float g_whhT[4 * HH * GG];
__device__ float g_wl1T[456 * HH];
__device__ float g_pooled[BB * HH];
__device__ __nv_bfloat16 g_Ahi[(size_t)MM * KP];
__device__ __nv_bfloat16 g_Alo[(size_t)MM * KP];
__device__ __nv_bfloat16 g_W[4 * 2 * GG * KP];   // [proj][hi/lo][512][256]

__device__ __forceinline__ float sigmoidf_(float x) { return 1.f / (1.f + expf(-x)); }

__device__ __forceinline__ void atomicMaxF(float* addr, float v) {
    if (v >= 0.f) atomicMax((int*)addr, __float_as_int(v));
    else          atomicMin((unsigned int*)addr, __float_as_uint(v));
}

// ================= PTX helpers (baseline sm_103 family: HMMA + ldmatrix + cp.async) =================
__device__ __forceinline__ uint32_t smem_u32(const void* p) {
    uint32_t addr;
    asm("{ .reg .u64 tmp; cvta.to.shared.u64 tmp, %1; cvt.u32.u64 %0, tmp; }"
        : "=r"(addr) : "l"(p));
    return addr;
}
#define CP_ASYNC16(dst, src) \
    asm volatile("cp.async.ca.shared.global [%0], [%1], 16;" :: "r"(dst), "l"(src))
#define CP_COMMIT() asm volatile("cp.async.commit_group;" ::: "memory")
#define CP_WAIT1()  asm volatile("cp.async.wait_group 1;" ::: "memory")
#define CP_WAIT0()  asm volatile("cp.async.wait_group 0;" ::: "memory")

__device__ __forceinline__ void ldsm_x4(uint32_t& r0, uint32_t& r1, uint32_t& r2, uint32_t& r3,
                                        uint32_t addr) {
    asm volatile("ldmatrix.sync.aligned.m8n8.x4.shared.b16 {%0,%1,%2,%3}, [%4];"
        : "=r"(r0), "=r"(r1), "=r"(r2), "=r"(r3) : "r"(addr));
}
__device__ __forceinline__ void mma16816(float* d, const uint32_t* a, uint32_t b0, uint32_t b1) {
    asm volatile(
        "mma.sync.aligned.m16n8k16.row.col.f32.bf16.bf16.f32 "
        "{%0,%1,%2,%3}, {%4,%5,%6,%7}, {%8,%9}, {%0,%1,%2,%3};"
        : "+f"(d[0]), "+f"(d[1]), "+f"(d[2]), "+f"(d[3])
        : "r"(a[0]), "r"(a[1]), "r"(a[2]), "r"(a[3]), "r"(b0), "r"(b1));
}

// ---------------- small helpers ----------------
__global__ void transpose_kernel(const float* __restrict__ in, float* __restrict__ out,
                                 int rows, int cols) {
    int idx = blockIdx.x * blockDim.x + threadIdx.x;
    if (idx < rows * cols) {
        int r = idx / cols, c = idx % cols;
        out[c * rows + r] = in[idx];
    }
}
__global__ void init_pooled_kernel(float* __restrict__ p) {
    int idx = blockIdx.x * blockDim.x + threadIdx.x;
    if (idx < BB * HH) p[idx] = -2.0f;
}

// ---------------- fp32 -> bf16 hi/lo conversions ----------------
__global__ void conv_bx_kernel(const float* __restrict__ bx,
                               __nv_bfloat16* __restrict__ hi, __nv_bfloat16* __restrict__ lo) {
    size_t idx = (size_t)blockIdx.x * blockDim.x + threadIdx.x;
    if (idx >= (size_t)MM * KP) return;
    int m = (int)(idx >> 8), k = (int)(idx & 255);
    int t = m >> 9, b = m & 511;
    float v = (k < DD) ? bx[(size_t)b * TN * DD + (size_t)t * DD + k] : 0.f;
    __nv_bfloat16 h = __float2bfloat16(v);
    hi[idx] = h;
    lo[idx] = __float2bfloat16(v - __bfloat162float(h));
}
__global__ void conv_lin_kernel(const float* __restrict__ src,
                                __nv_bfloat16* __restrict__ hi, __nv_bfloat16* __restrict__ lo,
                                size_t n) {
    size_t idx = (size_t)blockIdx.x * blockDim.x + threadIdx.x;
    if (idx >= n) return;
    float v = src[idx];
    __nv_bfloat16 h = __float2bfloat16(v);
    hi[idx] = h;
    lo[idx] = __float2bfloat16(v - __bfloat162float(h));
}
__global__ void conv_w_kernel(const float* __restrict__ w, int K,
                              __nv_bfloat16* __restrict__ hi, __nv_bfloat16* __restrict__ lo) {
    int idx = blockIdx.x * blockDim.x + threadIdx.x;
    if (idx >= GG * KP) return;
    int n = idx >> 8, k = idx & 255;
    float v = (k < K) ? w[(size_t)n * K + k] : 0.f;
    __nv_bfloat16 h = __float2bfloat16(v);
    hi[idx] = h;
    lo[idx] = __float2bfloat16(v - __bfloat162float(h));
}

// ---------------- HMMA projection GEMM ----------------
// C[m][512] = A[m][:K] @ W^T + b1 + b2 via bf16 split (hi*hi + hi*lo + lo*hi),
// K-concatenated into 3 segments; kchunks 32-wide chunks per segment.
// CTA 128x128, 8 warps (4m x 2n), warp tile 32x64 = 2x8 m16n8k16 MMAs.
#define SROW 80   // padded SMEM row stride in bytes (64B data + 16B pad)
__global__ __launch_bounds__(256) void proj_mma(
    const __nv_bfloat16* __restrict__ Ahi, const __nv_bfloat16* __restrict__ Alo,
    const __nv_bfloat16* __restrict__ Whi, const __nv_bfloat16* __restrict__ Wlo,
    const float* __restrict__ b1, const float* __restrict__ b2,
    float* __restrict__ C, int kchunks) {
    __shared__ __align__(16) unsigned char sA[2][128 * SROW];
    __shared__ __align__(16) unsigned char sB[2][128 * SROW];
    __shared__ float bias[128];
    int tid = threadIdx.x, lane = tid & 31, wid = tid >> 5;
    int wm = wid & 3, wn = wid >> 2;
    int m0 = blockIdx.y * 128, n0 = blockIdx.x * 128;
    if (tid < 128) bias[tid] = b1[n0 + tid] + b2[n0 + tid];

    uint32_t sa0 = smem_u32(sA), sb0 = smem_u32(sB);
    const __nv_bfloat16* Asegs[3] = { Ahi, Ahi, Alo };
    const __nv_bfloat16* Wsegs[3] = { Whi, Wlo, Whi };
    int total = 3 * kchunks;

    auto load_chunk = [&](int c, int buf) {
        int seg = c / kchunks;
        int ko = (c - seg * kchunks) * 32;
        const __nv_bfloat16* As = Asegs[seg] + (size_t)m0 * KP + ko;
        const __nv_bfloat16* Ws = Wsegs[seg] + (size_t)n0 * KP + ko;
#pragma unroll
        for (int i = 0; i < 2; i++) {
            int idx = tid + i * 256;
            int row = idx >> 2, w = idx & 3;
            CP_ASYNC16(sa0 + buf * (128 * SROW) + row * SROW + w * 16,
                       As + (size_t)row * KP + w * 8);
            CP_ASYNC16(sb0 + buf * (128 * SROW) + row * SROW + w * 16,
                       Ws + (size_t)row * KP + w * 8);
        }
        CP_COMMIT();
    };

    float acc[2][8][4] = {};
    load_chunk(0, 0);
    load_chunk(1, 1);

    for (int c = 0; c < total; c++) {
        int buf = c & 1;
        if (c + 1 < total) CP_WAIT1(); else CP_WAIT0();
        __syncthreads();
        uint32_t ab = sa0 + buf * (128 * SROW);
        uint32_t bb = sb0 + buf * (128 * SROW);
#pragma unroll
        for (int ks = 0; ks < 2; ks++) {
            uint32_t a[2][4], b[4][4];
#pragma unroll
            for (int mt = 0; mt < 2; mt++) {
                uint32_t addr = ab + (uint32_t)(wm * 32 + mt * 16 + (lane & 15)) * SROW
                                   + (uint32_t)(ks * 16 + ((lane & 16) ? 8 : 0)) * 2;
                ldsm_x4(a[mt][0], a[mt][1], a[mt][2], a[mt][3], addr);
            }
#pragma unroll
            for (int np = 0; np < 4; np++) {
                uint32_t addr = bb + (uint32_t)(wn * 64 + np * 16 + (lane & 7) + ((lane & 16) ? 8 : 0)) * SROW
                                   + (uint32_t)(ks * 16 + ((lane & 8) ? 8 : 0)) * 2;
                ldsm_x4(b[np][0], b[np][1], b[np][2], b[np][3], addr);
            }
#pragma unroll
            for (int mt = 0; mt < 2; mt++)
#pragma unroll
                for (int nt = 0; nt < 8; nt++)
                    mma16816(acc[mt][nt], a[mt], b[nt >> 1][(nt & 1) * 2],
                             b[nt >> 1][(nt & 1) * 2 + 1]);
        }
        __syncthreads();
        if (c + 2 < total) load_chunk(c + 2, buf);
    }

    // Epilogue: d0,d1 = (row lane/4, col 2*(lane%4)+{0,1}); d2,d3 = row+8.
#pragma unroll
    for (int mt = 0; mt < 2; mt++)
#pragma unroll
        for (int nt = 0; nt < 8; nt++) {
            int row  = m0 + wm * 32 + mt * 16 + (lane >> 2);
            int colL = wn * 64 + nt * 8 + (lane & 3) * 2;
            int col  = n0 + colL;
            float2 v0 = { acc[mt][nt][0] + bias[colL], acc[mt][nt][1] + bias[colL + 1] };
            float2 v1 = { acc[mt][nt][2] + bias[colL], acc[mt][nt][3] + bias[colL + 1] };
            *(float2*)(C + (size_t)row * 512 + col) = v0;
            *(float2*)(C + (size_t)(row + 8) * 512 + col) = v1;
        }
}

// ---------------- fused bidirectional LSTM recurrence ----------------
__global__ __launch_bounds__(256) void lstm_kernel(
    const float* __restrict__ xpF, const float* __restrict__ xpB,
    const float* __restrict__ whhTF, const float* __restrict__ whhTB,
    const float* __restrict__ hf,
    float* __restrict__ outF, float* __restrict__ outB, int outStride) {
    __shared__ float hsh[2][8][HH];
    int dir = blockIdx.x & 1;
    int rb = (blockIdx.x >> 1) * 8;
    const float* xp   = dir ? xpB   : xpF;
    const float* whhT = dir ? whhTB : whhTF;
    float*       out  = dir ? outB  : outF;
    int tid = threadIdx.x;
    int hcol = tid & 127;
    int r0 = (tid >> 7) * 4;
    float hfv = hf[hcol];
    float c[4];
#pragma unroll
    for (int r = 0; r < 4; r++) { c[r] = hfv; hsh[0][r0 + r][hcol] = hfv; }
    __syncthreads();

    for (int t = 0; t < TN; t++) {
        int tef = dir ? (TN - 1 - t) : t;
        int cur = t & 1;
        float acc[4][4];
        size_t rowbase = ((size_t)tef * BB + rb + r0) * GG + hcol;
#pragma unroll
        for (int r = 0; r < 4; r++) {
            const float* xr = xp + rowbase + (size_t)r * GG;
            acc[r][0] = xr[0];   acc[r][1] = xr[128];
            acc[r][2] = xr[256]; acc[r][3] = xr[384];
        }
        const float* wp = whhT + hcol;
#pragma unroll 4
        for (int k = 0; k < HH; k++) {
            float w0 = wp[0], w1 = wp[128], w2 = wp[256], w3 = wp[384];
            wp += GG;
#pragma unroll
            for (int r = 0; r < 4; r++) {
                float hv = hsh[cur][r0 + r][k];
                acc[r][0] += hv * w0; acc[r][1] += hv * w1;
                acc[r][2] += hv * w2; acc[r][3] += hv * w3;
            }
        }
#pragma unroll
        for (int r = 0; r < 4; r++) {
            float ig = sigmoidf_(acc[r][0]);
            float fg = sigmoidf_(acc[r][1]);
            float cc = tanhf(acc[r][2]);
            float og = sigmoidf_(acc[r][3]);
            float cv = fg * c[r] + ig * cc;
            c[r] = cv;
            float hv = og * tanhf(cv);
            hsh[cur ^ 1][r0 + r][hcol] = hv;
            out[((size_t)tef * BB + rb + r0 + r) * outStride + hcol] = hv;
        }
        __syncthreads();
    }
}

// ---------------- classifier: h = tanh(data @ w_l1^T), max over t ----------------
#define CTT 16
__global__ __launch_bounds__(256) void cls_kernel(
    const float* __restrict__ f1, const float* __restrict__ r1,
    const float* __restrict__ bx, const float* __restrict__ hf,
    const float* __restrict__ wl1T, float* __restrict__ pooled) {
    __shared__ float ds[CTT][456];
    int b = blockIdx.x;
    int tile = blockIdx.y;
    int tid = threadIdx.x;
    for (int idx = tid; idx < CTT * 456; idx += 256) {
        int tt = idx / 456, f = idx % 456;
        int t = tile * CTT + tt;
        float v = 0.f;
        if (t < TN) {
            if (f < 128) {
                v = (t == 0) ? hf[f] : f1[((size_t)t * BB + b) * HH + f];
            } else if (f < 328) {
                v = bx[(size_t)b * TN * DD + (size_t)t * DD + (f - 128)];
            } else {
                int j = f - 328;
                v = (t == TN - 1) ? hf[j] : r1[((size_t)(TN - 2 - t) * BB + b) * HH + j];
            }
        }
        ds[tt][f] = v;
    }
    __syncthreads();

    int o2 = (tid & 63) * 2;
    int tsub = tid >> 6;
    float acc[4][2];
#pragma unroll
    for (int q = 0; q < 4; q++) { acc[q][0] = 0.f; acc[q][1] = 0.f; }
    for (int f = 0; f < 456; f++) {
        float2 w = *(const float2*)(wl1T + f * HH + o2);
#pragma unroll
        for (int q = 0; q < 4; q++) {
            float dv = ds[tsub + q * 4][f];
            acc[q][0] += dv * w.x;
            acc[q][1] += dv * w.y;
        }
    }
    float m0v = -2.f, m1v = -2.f;
#pragma unroll
    for (int q = 0; q < 4; q++) {
        int t = tile * CTT + tsub + q * 4;
        if (t < TN) {
            m0v = fmaxf(m0v, tanhf(acc[q][0]));
            m1v = fmaxf(m1v, tanhf(acc[q][1]));
        }
    }
    atomicMaxF(&pooled[b * HH + o2],     m0v);
    atomicMaxF(&pooled[b * HH + o2 + 1], m1v);
}

// ---------------- final head ----------------
__global__ void out_kernel(const float* __restrict__ pooled,
                           const float* __restrict__ wl2, const float* __restrict__ bl2,
                           const int* __restrict__ by, float* __restrict__ outb,
                           int out_size) {
    __shared__ float sh[128];
    int b = blockIdx.x, tid = threadIdx.x;
    float p = pooled[b * 128 + tid];
    for (int o = 0; o < 4; o++) {
        float v = p * wl2[o * 128 + tid];
        sh[tid] = v;
        __syncthreads();
        if (tid < 64) sh[tid] += sh[tid + 64];
        __syncthreads();
        if (tid < 32) {
            float s = sh[tid] + sh[tid + 32];
            for (int off = 16; off; off >>= 1) s += __shfl_down_sync(0xffffffffu, s, off);
            if (tid == 0) outb[b * 4 + o] = s + bl2[o];
        }
        __syncthreads();
    }
    if (tid == 0 && out_size >= BB * 4 + BB) outb[BB * 4 + b] = (float)by[b];
}

// ---------------- launch ----------------
extern "C" void kernel_launch(void* const* d_in, const int* in_sizes, int n_in,
                              void* d_out, int out_size) {
    const float* bx       = (const float*)d_in[0];
    const int*   by       = (const int*)  d_in[1];
    const float* hf       = (const float*)d_in[2];
    const float* w_ih[4]  = { (const float*)d_in[3],  (const float*)d_in[7],
                              (const float*)d_in[11], (const float*)d_in[15] };
    const float* w_hh[4]  = { (const float*)d_in[4],  (const float*)d_in[8],
                              (const float*)d_in[12], (const float*)d_in[16] };
    const float* b_ih[4]  = { (const float*)d_in[5],  (const float*)d_in[9],
                              (const float*)d_in[13], (const float*)d_in[17] };
    const float* b_hh[4]  = { (const float*)d_in[6],  (const float*)d_in[10],
                              (const float*)d_in[14], (const float*)d_in[18] };
    const float* wl1      = (const float*)d_in[19];
    const float* wl2      = (const float*)d_in[20];
    const float* bl2      = (const float*)d_in[21];
    float* outb = (float*)d_out;

    float *xpA, *xpB, *y0, *f1, *r1, *whhT, *wl1T, *pooled;
    __nv_bfloat16 *Ahi, *Alo, *Wb;
    cudaGetSymbolAddress((void**)&xpA,    g_xpA);
    cudaGetSymbolAddress((void**)&xpB,    g_xpB);
    cudaGetSymbolAddress((void**)&y0,     g_y0);
    cudaGetSymbolAddress((void**)&f1,     g_f1);
    cudaGetSymbolAddress((void**)&r1,     g_r1);
    cudaGetSymbolAddress((void**)&whhT,   g_whhT);
    cudaGetSymbolAddress((void**)&wl1T,   g_wl1T);
    cudaGetSymbolAddress((void**)&pooled, g_pooled);
    cudaGetSymbolAddress((void**)&Ahi,    g_Ahi);
    cudaGetSymbolAddress((void**)&Alo,    g_Alo);
    cudaGetSymbolAddress((void**)&Wb,     g_W);

    // Pre-transposes + pooled init + weight conversions
    for (int i = 0; i < 4; i++)
        transpose_kernel<<<(GG * HH + 255) / 256, 256>>>(w_hh[i], whhT + i * GG * HH, GG, HH);
    transpose_kernel<<<(HH * 456 + 255) / 256, 256>>>(wl1, wl1T, HH, 456);
    init_pooled_kernel<<<(BB * HH + 255) / 256, 256>>>(pooled);
    int wK[4] = { DD, DD, 2 * HH, 2 * HH };
    for (int i = 0; i < 4; i++)
        conv_w_kernel<<<(GG * KP + 255) / 256, 256>>>(
            w_ih[i], wK[i], Wb + (size_t)(2 * i) * GG * KP, Wb + (size_t)(2 * i + 1) * GG * KP);

    dim3 pg(GG / 128, MM / 128);  // (4, 1200): N fastest for A-tile L2 reuse
    int kc0 = (DD + 31) / 32;     // 7 chunks cover K=200 (padded w/ zeros to 224)
    int kc1 = (2 * HH) / 32;      // 8

    // Layer 0: convert b_x, project both directions
    conv_bx_kernel<<<(int)(((size_t)MM * KP + 255) / 256), 256>>>(bx, Ahi, Alo);
    proj_mma<<<pg, 256>>>(Ahi, Alo, Wb, Wb + (size_t)GG * KP, b_ih[0], b_hh[0], xpA, kc0);
    proj_mma<<<pg, 256>>>(Ahi, Alo, Wb + (size_t)2 * GG * KP, Wb + (size_t)3 * GG * KP,
                          b_ih[1], b_hh[1], xpB, kc0);

    // Layer 0 recurrence -> y0 [t][b][256]
    lstm_kernel<<<128, 256>>>(xpA, xpB, whhT, whhT + GG * HH, hf, y0, y0 + HH, 2 * HH);

    // Layer 1: convert y0 (already [m][256] layout), project
    conv_lin_kernel<<<(int)(((size_t)MM * KP + 255) / 256), 256>>>(y0, Ahi, Alo, (size_t)MM * KP);
    proj_mma<<<pg, 256>>>(Ahi, Alo, Wb + (size_t)4 * GG * KP, Wb + (size_t)5 * GG * KP,
                          b_ih[2], b_hh[2], xpA, kc1);
    proj_mma<<<pg, 256>>>(Ahi, Alo, Wb + (size_t)6 * GG * KP, Wb + (size_t)7 * GG * KP,
                          b_ih[3], b_hh[3], xpB, kc1);

    // Layer 1 recurrence -> f1, r1
    lstm_kernel<<<128, 256>>>(xpA, xpB, whhT + 2 * GG * HH, whhT + 3 * GG * HH, hf, f1, r1, HH);

    // Classifier + maxpool
    dim3 cg(BB, (TN + CTT - 1) / CTT);
    cls_kernel<<<cg, 256>>>(f1, r1, bx, hf, wl1T, pooled);

    // Head + b_y passthrough
    out_kernel<<<BB, 128>>>(pooled, wl2, bl2, by, outb, out_size);
}

// round 4
// speedup vs baseline: 2.0889x; 1.7849x over previous
#include <cuda_runtime.h>
#include <cuda_bf16.h>
#include <math.h>
#include <cstdint>

// Problem dims
#define BB 512
#define TN 300
#define DD 200
#define HH 128
#define GG 512   // 4*H
#define MM (TN*BB)      // 153600 rows
#define KP 256          // padded K per segment

// ---------------- static device scratch ----------------
__device__ float g_xpA[(size_t)TN * BB * GG];
__device__ float g_xpB[(size_t)TN * BB * GG];
__device__ float g_y0 [(size_t)TN * BB * 2 * HH];
__device__ float g_f1 [(size_t)TN * BB * HH];
__device__ float g_r1 [(size_t)TN * BB * HH];
__device__ float4 g_whhT4[4 * HH * HH];          // [mat][k][h] -> (g0,g1,g2,g3)
__device__ float g_wl1T[456 * HH];
__device__ float g_pooled[BB * HH];
__device__ __nv_bfloat16 g_Ahi[(size_t)MM * KP];
__device__ __nv_bfloat16 g_Alo[(size_t)MM * KP];
__device__ __nv_bfloat16 g_W[4 * 2 * GG * KP];   // [proj][hi/lo][512][256]

__device__ __forceinline__ float sigmoidf_(float x) { return 1.f / (1.f + expf(-x)); }

__device__ __forceinline__ void atomicMaxF(float* addr, float v) {
    if (v >= 0.f) atomicMax((int*)addr, __float_as_int(v));
    else          atomicMin((unsigned int*)addr, __float_as_uint(v));
}

// ================= PTX helpers =================
__device__ __forceinline__ uint32_t smem_u32(const void* p) {
    uint32_t addr;
    asm("{ .reg .u64 tmp; cvta.to.shared.u64 tmp, %1; cvt.u32.u64 %0, tmp; }"
        : "=r"(addr) : "l"(p));
    return addr;
}
#define CP_ASYNC16(dst, src) \
    asm volatile("cp.async.ca.shared.global [%0], [%1], 16;" :: "r"(dst), "l"(src))
#define CP_COMMIT() asm volatile("cp.async.commit_group;" ::: "memory")
#define CP_WAIT1()  asm volatile("cp.async.wait_group 1;" ::: "memory")
#define CP_WAIT0()  asm volatile("cp.async.wait_group 0;" ::: "memory")

__device__ __forceinline__ void ldsm_x4(uint32_t& r0, uint32_t& r1, uint32_t& r2, uint32_t& r3,
                                        uint32_t addr) {
    asm volatile("ldmatrix.sync.aligned.m8n8.x4.shared.b16 {%0,%1,%2,%3}, [%4];"
        : "=r"(r0), "=r"(r1), "=r"(r2), "=r"(r3) : "r"(addr));
}
__device__ __forceinline__ void mma16816(float* d, const uint32_t* a, uint32_t b0, uint32_t b1) {
    asm volatile(
        "mma.sync.aligned.m16n8k16.row.col.f32.bf16.bf16.f32 "
        "{%0,%1,%2,%3}, {%4,%5,%6,%7}, {%8,%9}, {%0,%1,%2,%3};"
        : "+f"(d[0]), "+f"(d[1]), "+f"(d[2]), "+f"(d[3])
        : "r"(a[0]), "r"(a[1]), "r"(a[2]), "r"(a[3]), "r"(b0), "r"(b1));
}

// Packed fp32 pair (FFMA2) helpers
typedef unsigned long long u64t;
__device__ __forceinline__ u64t pack2(float a, float b) {
    u64t r; asm("mov.b64 %0, {%1,%2};" : "=l"(r) : "f"(a), "f"(b)); return r;
}
__device__ __forceinline__ void unpack2(u64t v, float& a, float& b) {
    asm("mov.b64 {%0,%1}, %2;" : "=f"(a), "=f"(b) : "l"(v));
}
__device__ __forceinline__ u64t fma2(u64t a, u64t b, u64t c) {
    u64t d; asm("fma.rn.f32x2 %0, %1, %2, %3;" : "=l"(d) : "l"(a), "l"(b), "l"(c)); return d;
}

// ---------------- fused prep: whhT4 (x4), wl1T, pooled init ----------------
__global__ void prep_kernel(const float* __restrict__ w0, const float* __restrict__ w1,
                            const float* __restrict__ w2, const float* __restrict__ w3,
                            const float* __restrict__ wl1,
                            float4* __restrict__ whhT4, float* __restrict__ wl1T,
                            float* __restrict__ pooled) {
    int idx = blockIdx.x * blockDim.x + threadIdx.x;
    if (idx < 4 * HH * HH) {
        int mat = idx >> 14, rem = idx & 16383;
        int k = rem >> 7, h = rem & 127;
        const float* w = (mat == 0) ? w0 : (mat == 1) ? w1 : (mat == 2) ? w2 : w3;
        whhT4[idx] = make_float4(w[(0   + h) * HH + k], w[(128 + h) * HH + k],
                                 w[(256 + h) * HH + k], w[(384 + h) * HH + k]);
    }
    if (idx < 456 * HH) {
        int f = idx >> 7, o = idx & 127;
        wl1T[idx] = wl1[o * 456 + f];
    }
    if (idx < BB * HH) pooled[idx] = -2.0f;
}

// ---------------- fp32 -> bf16 hi/lo conversions ----------------
__global__ void conv_bx_kernel(const float* __restrict__ bx,
                               __nv_bfloat16* __restrict__ hi, __nv_bfloat16* __restrict__ lo) {
    size_t idx = (size_t)blockIdx.x * blockDim.x + threadIdx.x;
    if (idx >= (size_t)MM * KP) return;
    int m = (int)(idx >> 8), k = (int)(idx & 255);
    int t = m >> 9, b = m & 511;
    float v = (k < DD) ? bx[(size_t)b * TN * DD + (size_t)t * DD + k] : 0.f;
    __nv_bfloat16 h = __float2bfloat16(v);
    hi[idx] = h;
    lo[idx] = __float2bfloat16(v - __bfloat162float(h));
}
__global__ void conv_lin_kernel(const float* __restrict__ src,
                                __nv_bfloat16* __restrict__ hi, __nv_bfloat16* __restrict__ lo,
                                size_t n) {
    size_t idx = (size_t)blockIdx.x * blockDim.x + threadIdx.x;
    if (idx >= n) return;
    float v = src[idx];
    __nv_bfloat16 h = __float2bfloat16(v);
    hi[idx] = h;
    lo[idx] = __float2bfloat16(v - __bfloat162float(h));
}
// all 4 weights in one kernel: out layout [proj][hi/lo][512][256]
__global__ void conv_w_all(const float* __restrict__ w0, const float* __restrict__ w1,
                           const float* __restrict__ w2, const float* __restrict__ w3,
                           __nv_bfloat16* __restrict__ out) {
    int idx = blockIdx.x * blockDim.x + threadIdx.x;
    if (idx >= 4 * GG * KP) return;
    int p = idx / (GG * KP), rem = idx % (GG * KP);
    int n = rem >> 8, k = rem & 255;
    const float* w = (p == 0) ? w0 : (p == 1) ? w1 : (p == 2) ? w2 : w3;
    int K = (p < 2) ? DD : 2 * HH;
    float v = (k < K) ? w[(size_t)n * K + k] : 0.f;
    __nv_bfloat16 h = __float2bfloat16(v);
    out[(size_t)(2 * p) * GG * KP + rem] = h;
    out[(size_t)(2 * p + 1) * GG * KP + rem] = __float2bfloat16(v - __bfloat162float(h));
}

// ---------------- HMMA projection GEMM ----------------
// C[m][512] = A[m][:] @ W^T + b1 + b2 via bf16 split; 3 segments x 4 chunks of K=64.
// CTA 128x128, 8 warps (4m x 2n), warp tile 32x64.
#define SROW 144          // 128B data + 16B pad
#define TILE_B (128 * SROW)   // 18432 per buffer per matrix
#define SMEM_PROJ (4 * TILE_B)
__global__ __launch_bounds__(256) void proj_mma(
    const __nv_bfloat16* __restrict__ Ahi, const __nv_bfloat16* __restrict__ Alo,
    const __nv_bfloat16* __restrict__ Whi, const __nv_bfloat16* __restrict__ Wlo,
    const float* __restrict__ b1, const float* __restrict__ b2,
    float* __restrict__ C) {
    extern __shared__ __align__(16) unsigned char dsm[];
    __shared__ float bias[128];
    int tid = threadIdx.x, lane = tid & 31, wid = tid >> 5;
    int wm = wid & 3, wn = wid >> 2;
    int m0 = blockIdx.y * 128, n0 = blockIdx.x * 128;
    if (tid < 128) bias[tid] = b1[n0 + tid] + b2[n0 + tid];

    uint32_t sa0 = smem_u32(dsm);             // A: 2 buffers
    uint32_t sb0 = sa0 + 2 * TILE_B;          // B: 2 buffers
    const __nv_bfloat16* Asegs[3] = { Ahi, Ahi, Alo };
    const __nv_bfloat16* Wsegs[3] = { Whi, Wlo, Whi };
    const int total = 12;  // 3 segments x 4 chunks (K=64 each, KP=256 zero-padded)

    auto load_chunk = [&](int c, int buf) {
        int seg = c >> 2;
        int ko = (c & 3) * 64;
        const __nv_bfloat16* As = Asegs[seg] + (size_t)m0 * KP + ko;
        const __nv_bfloat16* Ws = Wsegs[seg] + (size_t)n0 * KP + ko;
#pragma unroll
        for (int i = 0; i < 4; i++) {
            int idx = tid + i * 256;              // 1024 x 16B chunks
            int row = idx >> 3, w = idx & 7;
            CP_ASYNC16(sa0 + buf * TILE_B + row * SROW + w * 16,
                       As + (size_t)row * KP + w * 8);
            CP_ASYNC16(sb0 + buf * TILE_B + row * SROW + w * 16,
                       Ws + (size_t)row * KP + w * 8);
        }
        CP_COMMIT();
    };

    float acc[2][8][4] = {};
    load_chunk(0, 0);
    load_chunk(1, 1);

    for (int c = 0; c < total; c++) {
        int buf = c & 1;
        if (c + 1 < total) CP_WAIT1(); else CP_WAIT0();
        __syncthreads();
        uint32_t ab = sa0 + buf * TILE_B;
        uint32_t bb = sb0 + buf * TILE_B;
#pragma unroll
        for (int ks = 0; ks < 4; ks++) {
            uint32_t a[2][4], b[4][4];
#pragma unroll
            for (int mt = 0; mt < 2; mt++) {
                uint32_t addr = ab + (uint32_t)(wm * 32 + mt * 16 + (lane & 15)) * SROW
                                   + (uint32_t)(ks * 16 + ((lane & 16) ? 8 : 0)) * 2;
                ldsm_x4(a[mt][0], a[mt][1], a[mt][2], a[mt][3], addr);
            }
#pragma unroll
            for (int np = 0; np < 4; np++) {
                uint32_t addr = bb + (uint32_t)(wn * 64 + np * 16 + (lane & 7) + ((lane & 16) ? 8 : 0)) * SROW
                                   + (uint32_t)(ks * 16 + ((lane & 8) ? 8 : 0)) * 2;
                ldsm_x4(b[np][0], b[np][1], b[np][2], b[np][3], addr);
            }
#pragma unroll
            for (int mt = 0; mt < 2; mt++)
#pragma unroll
                for (int nt = 0; nt < 8; nt++)
                    mma16816(acc[mt][nt], a[mt], b[nt >> 1][(nt & 1) * 2],
                             b[nt >> 1][(nt & 1) * 2 + 1]);
        }
        __syncthreads();
        if (c + 2 < total) load_chunk(c + 2, buf);
    }

#pragma unroll
    for (int mt = 0; mt < 2; mt++)
#pragma unroll
        for (int nt = 0; nt < 8; nt++) {
            int row  = m0 + wm * 32 + mt * 16 + (lane >> 2);
            int colL = wn * 64 + nt * 8 + (lane & 3) * 2;
            int col  = n0 + colL;
            float2 v0 = { acc[mt][nt][0] + bias[colL], acc[mt][nt][1] + bias[colL + 1] };
            float2 v1 = { acc[mt][nt][2] + bias[colL], acc[mt][nt][3] + bias[colL + 1] };
            *(float2*)(C + (size_t)row * 512 + col) = v0;
            *(float2*)(C + (size_t)(row + 8) * 512 + col) = v1;
        }
}

// ---------------- fused bidirectional LSTM recurrence (FFMA2) ----------------
// grid 128 = 2 dirs x 64 slices (8 batch rows). thread: hcol = tid&127, 4 rows.
// Gates packed: acc01 = (i,f), acc23 = (c,o); whhT4[k][h] = (g0,g1,g2,g3).
__global__ __launch_bounds__(256) void lstm_kernel(
    const float* __restrict__ xpF, const float* __restrict__ xpB,
    const float4* __restrict__ whhT4F, const float4* __restrict__ whhT4B,
    const float* __restrict__ hf,
    float* __restrict__ outF, float* __restrict__ outB, int outStride) {
    __shared__ u64t hsh[2][8][HH];   // packed {h,h}
    int dir = blockIdx.x & 1;
    int rb = (blockIdx.x >> 1) * 8;
    const float*  xp   = dir ? xpB    : xpF;
    const float4* wT4  = dir ? whhT4B : whhT4F;
    float*        out  = dir ? outB   : outF;
    int tid = threadIdx.x;
    int hcol = tid & 127;
    int r0 = (tid >> 7) * 4;
    float hfv = hf[hcol];
    float c[4];
#pragma unroll
    for (int r = 0; r < 4; r++) { c[r] = hfv; hsh[0][r0 + r][hcol] = pack2(hfv, hfv); }
    __syncthreads();

    for (int t = 0; t < TN; t++) {
        int tef = dir ? (TN - 1 - t) : t;
        int cur = t & 1;
        u64t acc01[4], acc23[4];
        size_t rowbase = ((size_t)tef * BB + rb + r0) * GG + hcol;
#pragma unroll
        for (int r = 0; r < 4; r++) {
            const float* xr = xp + rowbase + (size_t)r * GG;
            acc01[r] = pack2(xr[0],   xr[128]);
            acc23[r] = pack2(xr[256], xr[384]);
        }
        const float4* wp = wT4 + hcol;
#pragma unroll 4
        for (int k = 0; k < HH; k++) {
            float4 w4 = *wp;
            wp += HH;
            u64t w01 = pack2(w4.x, w4.y);
            u64t w23 = pack2(w4.z, w4.w);
#pragma unroll
            for (int r = 0; r < 4; r++) {
                u64t h2 = hsh[cur][r0 + r][k];
                acc01[r] = fma2(h2, w01, acc01[r]);
                acc23[r] = fma2(h2, w23, acc23[r]);
            }
        }
#pragma unroll
        for (int r = 0; r < 4; r++) {
            float gi, gf, gc, go;
            unpack2(acc01[r], gi, gf);
            unpack2(acc23[r], gc, go);
            float ig = sigmoidf_(gi);
            float fg = sigmoidf_(gf);
            float cc = tanhf(gc);
            float og = sigmoidf_(go);
            float cv = fg * c[r] + ig * cc;
            c[r] = cv;
            float hv = og * tanhf(cv);
            hsh[cur ^ 1][r0 + r][hcol] = pack2(hv, hv);
            out[((size_t)tef * BB + rb + r0 + r) * outStride + hcol] = hv;
        }
        __syncthreads();
    }
}

// ---------------- classifier: h = tanh(data @ w_l1^T), max over t ----------------
#define CTT 16
__global__ __launch_bounds__(256) void cls_kernel(
    const float* __restrict__ f1, const float* __restrict__ r1,
    const float* __restrict__ bx, const float* __restrict__ hf,
    const float* __restrict__ wl1T, float* __restrict__ pooled) {
    __shared__ float ds[CTT][456];
    int b = blockIdx.x;
    int tile = blockIdx.y;
    int tid = threadIdx.x;
    for (int idx = tid; idx < CTT * 456; idx += 256) {
        int tt = idx / 456, f = idx % 456;
        int t = tile * CTT + tt;
        float v = 0.f;
        if (t < TN) {
            if (f < 128) {
                v = (t == 0) ? hf[f] : f1[((size_t)t * BB + b) * HH + f];
            } else if (f < 328) {
                v = bx[(size_t)b * TN * DD + (size_t)t * DD + (f - 128)];
            } else {
                int j = f - 328;
                v = (t == TN - 1) ? hf[j] : r1[((size_t)(TN - 2 - t) * BB + b) * HH + j];
            }
        }
        ds[tt][f] = v;
    }
    __syncthreads();

    int o2 = (tid & 63) * 2;
    int tsub = tid >> 6;
    float acc[4][2];
#pragma unroll
    for (int q = 0; q < 4; q++) { acc[q][0] = 0.f; acc[q][1] = 0.f; }
    for (int f = 0; f < 456; f++) {
        float2 w = *(const float2*)(wl1T + f * HH + o2);
#pragma unroll
        for (int q = 0; q < 4; q++) {
            float dv = ds[tsub + q * 4][f];
            acc[q][0] += dv * w.x;
            acc[q][1] += dv * w.y;
        }
    }
    float m0v = -2.f, m1v = -2.f;
#pragma unroll
    for (int q = 0; q < 4; q++) {
        int t = tile * CTT + tsub + q * 4;
        if (t < TN) {
            m0v = fmaxf(m0v, tanhf(acc[q][0]));
            m1v = fmaxf(m1v, tanhf(acc[q][1]));
        }
    }
    atomicMaxF(&pooled[b * HH + o2],     m0v);
    atomicMaxF(&pooled[b * HH + o2 + 1], m1v);
}

// ---------------- final head ----------------
__global__ void out_kernel(const float* __restrict__ pooled,
                           const float* __restrict__ wl2, const float* __restrict__ bl2,
                           const int* __restrict__ by, float* __restrict__ outb,
                           int out_size) {
    __shared__ float sh[128];
    int b = blockIdx.x, tid = threadIdx.x;
    float p = pooled[b * 128 + tid];
    for (int o = 0; o < 4; o++) {
        float v = p * wl2[o * 128 + tid];
        sh[tid] = v;
        __syncthreads();
        if (tid < 64) sh[tid] += sh[tid + 64];
        __syncthreads();
        if (tid < 32) {
            float s = sh[tid] + sh[tid + 32];
            for (int off = 16; off; off >>= 1) s += __shfl_down_sync(0xffffffffu, s, off);
            if (tid == 0) outb[b * 4 + o] = s + bl2[o];
        }
        __syncthreads();
    }
    if (tid == 0 && out_size >= BB * 4 + BB) outb[BB * 4 + b] = (float)by[b];
}

// ---------------- launch ----------------
extern "C" void kernel_launch(void* const* d_in, const int* in_sizes, int n_in,
                              void* d_out, int out_size) {
    const float* bx       = (const float*)d_in[0];
    const int*   by       = (const int*)  d_in[1];
    const float* hf       = (const float*)d_in[2];
    const float* w_ih[4]  = { (const float*)d_in[3],  (const float*)d_in[7],
                              (const float*)d_in[11], (const float*)d_in[15] };
    const float* w_hh[4]  = { (const float*)d_in[4],  (const float*)d_in[8],
                              (const float*)d_in[12], (const float*)d_in[16] };
    const float* b_ih[4]  = { (const float*)d_in[5],  (const float*)d_in[9],
                              (const float*)d_in[13], (const float*)d_in[17] };
    const float* b_hh[4]  = { (const float*)d_in[6],  (const float*)d_in[10],
                              (const float*)d_in[14], (const float*)d_in[18] };
    const float* wl1      = (const float*)d_in[19];
    const float* wl2      = (const float*)d_in[20];
    const float* bl2      = (const float*)d_in[21];
    float* outb = (float*)d_out;

    float *xpA, *xpB, *y0, *f1, *r1, *wl1T, *pooled;
    float4* whhT4;
    __nv_bfloat16 *Ahi, *Alo, *Wb;
    cudaGetSymbolAddress((void**)&xpA,    g_xpA);
    cudaGetSymbolAddress((void**)&xpB,    g_xpB);
    cudaGetSymbolAddress((void**)&y0,     g_y0);
    cudaGetSymbolAddress((void**)&f1,     g_f1);
    cudaGetSymbolAddress((void**)&r1,     g_r1);
    cudaGetSymbolAddress((void**)&whhT4,  g_whhT4);
    cudaGetSymbolAddress((void**)&wl1T,   g_wl1T);
    cudaGetSymbolAddress((void**)&pooled, g_pooled);
    cudaGetSymbolAddress((void**)&Ahi,    g_Ahi);
    cudaGetSymbolAddress((void**)&Alo,    g_Alo);
    cudaGetSymbolAddress((void**)&Wb,     g_W);

    cudaFuncSetAttribute(proj_mma, cudaFuncAttributeMaxDynamicSharedMemorySize, SMEM_PROJ);

    // 0: fused prep (whhT4 x4, wl1T, pooled init)
    prep_kernel<<<(4 * HH * HH + 255) / 256, 256>>>(
        w_hh[0], w_hh[1], w_hh[2], w_hh[3], wl1, whhT4, wl1T, pooled);
    // 1: all weight conversions
    conv_w_all<<<(4 * GG * KP + 255) / 256, 256>>>(w_ih[0], w_ih[1], w_ih[2], w_ih[3], Wb);
    // 2: input conversion
    conv_bx_kernel<<<(int)(((size_t)MM * KP + 255) / 256), 256>>>(bx, Ahi, Alo);

    dim3 pg(GG / 128, MM / 128);  // (4, 1200)

    // 3,4: layer-0 projections
    proj_mma<<<pg, 256, SMEM_PROJ>>>(Ahi, Alo, Wb, Wb + (size_t)GG * KP,
                                     b_ih[0], b_hh[0], xpA);
    proj_mma<<<pg, 256, SMEM_PROJ>>>(Ahi, Alo, Wb + (size_t)2 * GG * KP, Wb + (size_t)3 * GG * KP,
                                     b_ih[1], b_hh[1], xpB);
    // 5: layer-0 recurrence -> y0 [t][b][256]
    lstm_kernel<<<128, 256>>>(xpA, xpB, whhT4, whhT4 + HH * HH, hf, y0, y0 + HH, 2 * HH);

    // 6: convert y0; 7,8: layer-1 projections
    conv_lin_kernel<<<(int)(((size_t)MM * KP + 255) / 256), 256>>>(y0, Ahi, Alo, (size_t)MM * KP);
    proj_mma<<<pg, 256, SMEM_PROJ>>>(Ahi, Alo, Wb + (size_t)4 * GG * KP, Wb + (size_t)5 * GG * KP,
                                     b_ih[2], b_hh[2], xpA);
    proj_mma<<<pg, 256, SMEM_PROJ>>>(Ahi, Alo, Wb + (size_t)6 * GG * KP, Wb + (size_t)7 * GG * KP,
                                     b_ih[3], b_hh[3], xpB);
    // 9: layer-1 recurrence -> f1, r1
    lstm_kernel<<<128, 256>>>(xpA, xpB, whhT4 + 2 * HH * HH, whhT4 + 3 * HH * HH, hf, f1, r1, HH);

    // 10: classifier + maxpool
    dim3 cg(BB, (TN + CTT - 1) / CTT);
    cls_kernel<<<cg, 256>>>(f1, r1, bx, hf, wl1T, pooled);
    // 11: head + b_y passthrough
    out_kernel<<<BB, 128>>>(pooled, wl2, bl2, by, outb, out_size);
}